// round 6
// baseline (speedup 1.0000x reference)
#include <cuda_runtime.h>
#include <cuda_bf16.h>
#include <cstdint>
#include <math.h>

#define B_DIM 32
#define Q_DIM 32
#define P_DIM 196
#define D_DIM 1024
#define MROWS (B_DIM*Q_DIM)        // 1024
#define NCOLS (B_DIM*P_DIM)        // 6272
#define N4    (MROWS*NCOLS)

// ---------------- scratch ----------------
__device__ __nv_bfloat16 g_tn[MROWS * D_DIM];
__device__ __nv_bfloat16 g_vn[NCOLS * D_DIM];

// ---------------- kernel 1: row L2 normalize + f32->bf16 (both tensors) ----------------
__global__ __launch_bounds__(256) void normalize_kernel(const float* __restrict__ tf,
                                                        const float* __restrict__ vf)
{
    const int blk = blockIdx.x;
    const float* in;
    __nv_bfloat16* out;
    int row;
    if (blk < MROWS) { in = tf; out = g_tn; row = blk; }
    else             { in = vf; out = g_vn; row = blk - MROWS; }

    const int tid = threadIdx.x;
    const float4 v = reinterpret_cast<const float4*>(in + (size_t)row * D_DIM)[tid];
    float ss = v.x*v.x + v.y*v.y + v.z*v.z + v.w*v.w;
    #pragma unroll
    for (int o = 16; o; o >>= 1) ss += __shfl_xor_sync(0xffffffffu, ss, o);
    __shared__ float red[8];
    if ((tid & 31) == 0) red[tid >> 5] = ss;
    __syncthreads();
    if (tid == 0) {
        float t = 0.f;
        #pragma unroll
        for (int i = 0; i < 8; i++) t += red[i];
        red[0] = t;
    }
    __syncthreads();
    const float s = 1.0f / fmaxf(sqrtf(red[0]), 1e-8f);
    __nv_bfloat162 h0 = __floats2bfloat162_rn(v.x * s, v.y * s);
    __nv_bfloat162 h1 = __floats2bfloat162_rn(v.z * s, v.w * s);
    uint2 u;
    u.x = *reinterpret_cast<uint32_t*>(&h0);
    u.y = *reinterpret_cast<uint32_t*>(&h1);
    reinterpret_cast<uint2*>(out + (size_t)row * D_DIM)[tid] = u;
}

// ---------------- mma.sync helpers ----------------
__device__ __forceinline__ void cp_async16(uint32_t dst, const void* src) {
    asm volatile("cp.async.cg.shared.global [%0], [%1], 16;\n" :: "r"(dst), "l"(src));
}
__device__ __forceinline__ void ldsm_x4(uint32_t* r, uint32_t addr) {
    asm volatile("ldmatrix.sync.aligned.m8n8.x4.shared.b16 {%0,%1,%2,%3}, [%4];\n"
                 : "=r"(r[0]), "=r"(r[1]), "=r"(r[2]), "=r"(r[3]) : "r"(addr));
}
__device__ __forceinline__ void mma16816(float* c, const uint32_t* a, const uint32_t* b) {
    asm volatile("mma.sync.aligned.m16n8k16.row.col.f32.bf16.bf16.f32 "
                 "{%0,%1,%2,%3}, {%4,%5,%6,%7}, {%8,%9}, {%0,%1,%2,%3};\n"
                 : "+f"(c[0]), "+f"(c[1]), "+f"(c[2]), "+f"(c[3])
                 : "r"(a[0]), "r"(a[1]), "r"(a[2]), "r"(a[3]), "r"(b[0]), "r"(b[1]));
}

#define SSTR   40                    // padded bf16 row stride (80B)
#define BROWS  240                   // B smem rows (196 loaded; rest unread garbage, masked)
#define A_BYTES (128*SSTR*2)         // 10240
#define B_BYTES (BROWS*SSTR*2)       // 19200
#define SM_TOT  (2*A_BYTES + 2*B_BYTES)  // 58880

extern __shared__ char smem_raw[];

// ---------------- fused: GEMM (M=128, N=224 over one c) + dual softmax + combine ----------------
__global__ __launch_bounds__(256) void fused_kernel(
    const float* __restrict__ cpred,
    const int* __restrict__ tmask,
    const int* __restrict__ vmask,
    const int* __restrict__ cmask,
    float* __restrict__ out, int wmm, int wcp)
{
    const int tid  = threadIdx.x;
    const int lane = tid & 31;
    const int warp = tid >> 5;
    const int wm = warp >> 2;     // 0..1 (64 rows)
    const int wn = warp & 3;      // 0..3 (56 cols)
    const int c  = blockIdx.x;    // image 0..31
    const int bm = blockIdx.y;    // 0..7

    float acc[4][7][4];
    #pragma unroll
    for (int i = 0; i < 4; i++)
        #pragma unroll
        for (int j = 0; j < 7; j++)
            #pragma unroll
            for (int k = 0; k < 4; k++) acc[i][j][k] = 0.f;

    auto aPtr = [&](int buf) { return (__nv_bfloat16*)(smem_raw + buf * A_BYTES); };
    auto bPtr = [&](int buf) { return (__nv_bfloat16*)(smem_raw + 2 * A_BYTES + buf * B_BYTES); };

    auto load_chunk = [&](int kc, int buf) {
        __nv_bfloat16* sA = aPtr(buf);
        __nv_bfloat16* sB = bPtr(buf);
        // A: 128 rows x 4 x 16B = 512; B: 196 rows x 4 x 16B = 784; total 1296
        for (int i = tid; i < 1296; i += 256) {
            if (i < 512) {
                const int r = i >> 2, cc = i & 3;
                cp_async16((uint32_t)__cvta_generic_to_shared(&sA[r * SSTR + cc * 8]),
                           g_tn + (size_t)(bm * 128 + r) * D_DIM + kc * 32 + cc * 8);
            } else {
                const int j = i - 512;
                const int r = j >> 2, cc = j & 3;
                cp_async16((uint32_t)__cvta_generic_to_shared(&sB[r * SSTR + cc * 8]),
                           g_vn + (size_t)(c * P_DIM + r) * D_DIM + kc * 32 + cc * 8);
            }
        }
        asm volatile("cp.async.commit_group;\n");
    };

    load_chunk(0, 0);

    const int a_row  = lane & 15;
    const int a_koff = (lane >> 4) * 8;
    const int b_n    = ((lane >> 4) & 1) * 8 + (lane & 7);
    const int b_k    = ((lane >> 3) & 1) * 8;

    for (int kb = 0; kb < 32; kb++) {
        asm volatile("cp.async.wait_group 0;\n");
        __syncthreads();
        if (kb + 1 < 32) load_chunk(kb + 1, (kb + 1) & 1);
        const int buf = kb & 1;
        __nv_bfloat16* sA = aPtr(buf);
        __nv_bfloat16* sB = bPtr(buf);
        #pragma unroll
        for (int ks = 0; ks < 2; ks++) {
            uint32_t a[4][4], b[8][2];
            #pragma unroll
            for (int mt = 0; mt < 4; mt++) {
                int row = wm * 64 + mt * 16 + a_row;
                ldsm_x4(a[mt], (uint32_t)__cvta_generic_to_shared(
                    &sA[row * SSTR + ks * 16 + a_koff]));
            }
            #pragma unroll
            for (int bp = 0; bp < 4; bp++) {
                uint32_t r[4];
                int row = wn * 56 + bp * 16 + b_n;
                ldsm_x4(r, (uint32_t)__cvta_generic_to_shared(
                    &sB[row * SSTR + ks * 16 + b_k]));
                b[2 * bp][0] = r[0]; b[2 * bp][1] = r[1];
                b[2 * bp + 1][0] = r[2]; b[2 * bp + 1][1] = r[3];
            }
            #pragma unroll
            for (int mt = 0; mt < 4; mt++)
                #pragma unroll
                for (int nt = 0; nt < 7; nt++)
                    mma16816(acc[mt][nt], a[mt], b[nt]);
        }
        __syncthreads();
    }

    // ============ fused epilogue: dual masked softmax over p + combine ============
    __syncthreads();
    float2* redx = (float2*)smem_raw;          // [4][128] (max, sum)
    float2* redy = ((float2*)smem_raw) + 512;  // [4][128]

    const int rsub    = lane >> 2;       // 0..7
    const int cq      = (lane & 3) * 2;  // 0,2,4,6
    const int colbase = wn * 56;
    const float NEG = __int_as_float(0xff800000);

    // per-thread col validity (row-independent): bit = nt*2+j
    unsigned pb = 0, vb = 0;
    #pragma unroll
    for (int nt = 0; nt < 7; nt++)
        #pragma unroll
        for (int j = 0; j < 2; j++) {
            const int p = colbase + nt * 8 + cq + j;
            if (p < P_DIM) {
                pb |= 1u << (nt * 2 + j);
                if (vmask[c * P_DIM + p] != 0) vb |= 1u << (nt * 2 + j);
            }
        }

    // ---- pass 1: per-warp partial (max, sum) for both softmaxes ----
    #pragma unroll
    for (int mt = 0; mt < 4; mt++)
    #pragma unroll
    for (int h = 0; h < 2; h++) {
        const int mrow = wm * 64 + mt * 16 + h * 8 + rsub;
        const int bqr  = bm * 128 + mrow;
        const unsigned okb = (tmask[bqr] != 0) ? vb : 0u;

        // x (similarity) stats
        float mx = NEG;
        #pragma unroll
        for (int nt = 0; nt < 7; nt++)
            #pragma unroll
            for (int j = 0; j < 2; j++)
                if ((okb >> (nt * 2 + j)) & 1) mx = fmaxf(mx, acc[mt][nt][h * 2 + j]);
        mx = fmaxf(mx, __shfl_xor_sync(0xffffffffu, mx, 1));
        mx = fmaxf(mx, __shfl_xor_sync(0xffffffffu, mx, 2));
        float sx = 0.f;
        #pragma unroll
        for (int nt = 0; nt < 7; nt++)
            #pragma unroll
            for (int j = 0; j < 2; j++)
                if ((okb >> (nt * 2 + j)) & 1) sx += __expf(acc[mt][nt][h * 2 + j] - mx);
        sx += __shfl_xor_sync(0xffffffffu, sx, 1);
        sx += __shfl_xor_sync(0xffffffffu, sx, 2);
        if ((lane & 3) == 0) redx[wn * 128 + mrow] = make_float2(mx, sx);

        // y (concepts) stats
        const float* cpr = cpred + (size_t)bqr * NCOLS + c * P_DIM + colbase;
        const int*   cmr = cmask + (size_t)bqr * NCOLS + c * P_DIM + colbase;
        float yv[14];
        unsigned yb = 0;
        float my = NEG;
        #pragma unroll
        for (int nt = 0; nt < 7; nt++)
            #pragma unroll
            for (int j = 0; j < 2; j++) {
                const int bit = nt * 2 + j;
                float v = NEG;
                if ((pb >> bit) & 1) {
                    const int idx = nt * 8 + cq + j;
                    if (cmr[idx] != 0) { v = cpr[idx]; yb |= 1u << bit; }
                }
                yv[bit] = v;
                my = fmaxf(my, v);
            }
        my = fmaxf(my, __shfl_xor_sync(0xffffffffu, my, 1));
        my = fmaxf(my, __shfl_xor_sync(0xffffffffu, my, 2));
        float sy = 0.f;
        #pragma unroll
        for (int bit = 0; bit < 14; bit++)
            if ((yb >> bit) & 1) sy += __expf(yv[bit] - my);
        sy += __shfl_xor_sync(0xffffffffu, sy, 1);
        sy += __shfl_xor_sync(0xffffffffu, sy, 2);
        if ((lane & 3) == 0) redy[wn * 128 + mrow] = make_float2(my, sy);
    }
    __syncthreads();

    // ---- pass 2: merge warp partials, compute probs, write outputs ----
    #pragma unroll
    for (int mt = 0; mt < 4; mt++)
    #pragma unroll
    for (int h = 0; h < 2; h++) {
        const int mrow = wm * 64 + mt * 16 + h * 8 + rsub;
        const int bqr  = bm * 128 + mrow;
        const unsigned okb = (tmask[bqr] != 0) ? vb : 0u;

        float Mx = NEG, My = NEG;
        float2 px[4], py[4];
        #pragma unroll
        for (int w = 0; w < 4; w++) {
            px[w] = redx[w * 128 + mrow]; Mx = fmaxf(Mx, px[w].x);
            py[w] = redy[w * 128 + mrow]; My = fmaxf(My, py[w].x);
        }
        float Sx = 0.f, Sy = 0.f;
        #pragma unroll
        for (int w = 0; w < 4; w++) {
            Sx += px[w].y * __expf(px[w].x - Mx);
            Sy += py[w].y * __expf(py[w].x - My);
        }
        const float invSx = 1.f / Sx, invSy = 1.f / Sy;

        const size_t obase = (size_t)bqr * NCOLS + c * P_DIM + colbase;
        const float* cpr = cpred + obase;
        const int*   cmr = cmask + obase;
        #pragma unroll
        for (int nt = 0; nt < 7; nt++)
            #pragma unroll
            for (int j = 0; j < 2; j++) {
                const int bit = nt * 2 + j;
                if (!((pb >> bit) & 1)) continue;
                const int idx = nt * 8 + cq + j;
                const bool ok = (okb >> bit) & 1;
                const float xv = ok ? acc[mt][nt][h * 2 + j] : NEG;
                const float mmv = __expf(xv - Mx) * invSx;
                const bool m2 = cmr[idx] != 0;
                const float yvv = m2 ? cpr[idx] : NEG;
                const float cpv = __expf(yvv - My) * invSy;
                out[obase + idx] = (ok && m2) ? 0.5f * (mmv + cpv) : 0.f;
                if (wmm) out[(size_t)N4 + obase + idx] = mmv;
                if (wcp) out[2 * (size_t)N4 + obase + idx] = cpv;
            }
    }
}

// ---------------- launch ----------------
extern "C" void kernel_launch(void* const* d_in, const int* in_sizes, int n_in,
                              void* d_out, int out_size)
{
    const float* visual_feat   = (const float*)d_in[0];
    const int*   visual_mask   = (const int*)d_in[1];
    const float* textual_feat  = (const float*)d_in[2];
    const int*   textual_mask  = (const int*)d_in[3];
    const float* concepts_pred = (const float*)d_in[4];
    const int*   concepts_mask = (const int*)d_in[5];
    float* out = (float*)d_out;

    const int wmm = (out_size >= 2 * N4) ? 1 : 0;
    const int wcp = (out_size >= 3 * N4) ? 1 : 0;

    normalize_kernel<<<MROWS + NCOLS, 256>>>(textual_feat, visual_feat);

    cudaFuncSetAttribute(fused_kernel,
                         cudaFuncAttributeMaxDynamicSharedMemorySize, SM_TOT);
    dim3 fgrid(B_DIM, MROWS / 128);   // (32 images, 8 row-blocks)
    fused_kernel<<<fgrid, 256, SM_TOT>>>(concepts_pred, textual_mask, visual_mask,
                                         concepts_mask, out, wmm, wcp);
}

// round 7
// speedup vs baseline: 2.5246x; 2.5246x over previous
#include <cuda_runtime.h>
#include <cuda_bf16.h>
#include <cstdint>
#include <math.h>

#define B_DIM 32
#define Q_DIM 32
#define P_DIM 196
#define D_DIM 1024
#define MROWS (B_DIM*Q_DIM)        // 1024
#define NCOLS (B_DIM*P_DIM)        // 6272
#define N4    (MROWS*NCOLS)

// ---------------- scratch ----------------
__device__ __nv_bfloat16 g_tn[MROWS * D_DIM];
__device__ __nv_bfloat16 g_vn[NCOLS * D_DIM];
__device__ float         g_sim[(size_t)MROWS * NCOLS];

// ---------------- kernel 1: row L2 normalize + f32->bf16 (both tensors) ----------------
__global__ __launch_bounds__(256) void normalize_kernel(const float* __restrict__ tf,
                                                        const float* __restrict__ vf)
{
    const int blk = blockIdx.x;
    const float* in;
    __nv_bfloat16* out;
    int row;
    if (blk < MROWS) { in = tf; out = g_tn; row = blk; }
    else             { in = vf; out = g_vn; row = blk - MROWS; }

    const int tid = threadIdx.x;
    const float4 v = reinterpret_cast<const float4*>(in + (size_t)row * D_DIM)[tid];
    float ss = v.x*v.x + v.y*v.y + v.z*v.z + v.w*v.w;
    #pragma unroll
    for (int o = 16; o; o >>= 1) ss += __shfl_xor_sync(0xffffffffu, ss, o);
    __shared__ float red[8];
    if ((tid & 31) == 0) red[tid >> 5] = ss;
    __syncthreads();
    if (tid == 0) {
        float t = 0.f;
        #pragma unroll
        for (int i = 0; i < 8; i++) t += red[i];
        red[0] = t;
    }
    __syncthreads();
    const float s = 1.0f / fmaxf(sqrtf(red[0]), 1e-8f);
    __nv_bfloat162 h0 = __floats2bfloat162_rn(v.x * s, v.y * s);
    __nv_bfloat162 h1 = __floats2bfloat162_rn(v.z * s, v.w * s);
    uint2 u;
    u.x = *reinterpret_cast<uint32_t*>(&h0);
    u.y = *reinterpret_cast<uint32_t*>(&h1);
    reinterpret_cast<uint2*>(out + (size_t)row * D_DIM)[tid] = u;
}

// ---------------- kernel 2: bf16 tensor-core GEMM  C[M,N] = A[M,K] * B[N,K]^T ----------------
__device__ __forceinline__ void cp_async16(uint32_t dst, const void* src) {
    asm volatile("cp.async.cg.shared.global [%0], [%1], 16;\n" :: "r"(dst), "l"(src));
}
__device__ __forceinline__ void ldsm_x4(uint32_t* r, uint32_t addr) {
    asm volatile("ldmatrix.sync.aligned.m8n8.x4.shared.b16 {%0,%1,%2,%3}, [%4];\n"
                 : "=r"(r[0]), "=r"(r[1]), "=r"(r[2]), "=r"(r[3]) : "r"(addr));
}
__device__ __forceinline__ void mma16816(float* c, const uint32_t* a, const uint32_t* b) {
    asm volatile("mma.sync.aligned.m16n8k16.row.col.f32.bf16.bf16.f32 "
                 "{%0,%1,%2,%3}, {%4,%5,%6,%7}, {%8,%9}, {%0,%1,%2,%3};\n"
                 : "+f"(c[0]), "+f"(c[1]), "+f"(c[2]), "+f"(c[3])
                 : "r"(a[0]), "r"(a[1]), "r"(a[2]), "r"(a[3]), "r"(b[0]), "r"(b[1]));
}

#define SSTR 40   // padded bf16 stride: 80B/row

__global__ __launch_bounds__(256, 2) void gemm_kernel()
{
    __shared__ __nv_bfloat16 sA[2][128 * SSTR];
    __shared__ __nv_bfloat16 sB[2][128 * SSTR];
    const __nv_bfloat16* __restrict__ A  = g_tn;
    const __nv_bfloat16* __restrict__ Bm = g_vn;

    const int tid  = threadIdx.x;
    const int lane = tid & 31;
    const int warp = tid >> 5;
    const int wm = warp >> 2;   // 0..1  (64 rows each)
    const int wn = warp & 3;    // 0..3  (32 cols each)
    const int bm = blockIdx.y;  // 0..7
    const int bn = blockIdx.x;  // 0..48

    float acc[4][4][4];
    #pragma unroll
    for (int i = 0; i < 4; i++)
        #pragma unroll
        for (int j = 0; j < 4; j++)
            #pragma unroll
            for (int k = 0; k < 4; k++) acc[i][j][k] = 0.f;

    const int c0row = tid >> 2,          c0k = tid & 3;
    const int c1row = (tid + 256) >> 2;

    auto issue_load = [&](int buf, int kb) {
        const __nv_bfloat16* g;
        g = A + (size_t)(bm * 128 + c0row) * D_DIM + kb * 32 + c0k * 8;
        cp_async16((uint32_t)__cvta_generic_to_shared(&sA[buf][c0row * SSTR + c0k * 8]), g);
        g = A + (size_t)(bm * 128 + c1row) * D_DIM + kb * 32 + c0k * 8;
        cp_async16((uint32_t)__cvta_generic_to_shared(&sA[buf][c1row * SSTR + c0k * 8]), g);
        g = Bm + (size_t)(bn * 128 + c0row) * D_DIM + kb * 32 + c0k * 8;
        cp_async16((uint32_t)__cvta_generic_to_shared(&sB[buf][c0row * SSTR + c0k * 8]), g);
        g = Bm + (size_t)(bn * 128 + c1row) * D_DIM + kb * 32 + c0k * 8;
        cp_async16((uint32_t)__cvta_generic_to_shared(&sB[buf][c1row * SSTR + c0k * 8]), g);
    };

    issue_load(0, 0);
    asm volatile("cp.async.commit_group;\n");

    const int a_row  = lane & 15;
    const int a_koff = (lane >> 4) * 8;
    const int b_n    = ((lane >> 4) & 1) * 8 + (lane & 7);
    const int b_k    = ((lane >> 3) & 1) * 8;

    for (int kb = 0; kb < 32; kb++) {
        asm volatile("cp.async.wait_group 0;\n");
        __syncthreads();
        if (kb + 1 < 32) {
            issue_load((kb + 1) & 1, kb + 1);
            asm volatile("cp.async.commit_group;\n");
        }
        const int buf = kb & 1;
        #pragma unroll
        for (int ks = 0; ks < 2; ks++) {
            uint32_t a[4][4], b[4][2];
            #pragma unroll
            for (int mt = 0; mt < 4; mt++) {
                int row = wm * 64 + mt * 16 + a_row;
                ldsm_x4(a[mt], (uint32_t)__cvta_generic_to_shared(
                    &sA[buf][row * SSTR + ks * 16 + a_koff]));
            }
            #pragma unroll
            for (int bp = 0; bp < 2; bp++) {
                uint32_t r[4];
                int row = wn * 32 + bp * 16 + b_n;
                ldsm_x4(r, (uint32_t)__cvta_generic_to_shared(
                    &sB[buf][row * SSTR + ks * 16 + b_k]));
                b[2 * bp][0] = r[0]; b[2 * bp][1] = r[1];
                b[2 * bp + 1][0] = r[2]; b[2 * bp + 1][1] = r[3];
            }
            #pragma unroll
            for (int mt = 0; mt < 4; mt++)
                #pragma unroll
                for (int nt = 0; nt < 4; nt++)
                    mma16816(acc[mt][nt], a[mt], b[nt]);
        }
    }

    // epilogue: write f32 sims
    #pragma unroll
    for (int mt = 0; mt < 4; mt++) {
        const int m = bm * 128 + wm * 64 + mt * 16 + (lane >> 2);
        #pragma unroll
        for (int nt = 0; nt < 4; nt++) {
            const int n = bn * 128 + wn * 32 + nt * 8 + (lane & 3) * 2;
            *reinterpret_cast<float2*>(&g_sim[(size_t)m * NCOLS + n]) =
                make_float2(acc[mt][nt][0], acc[mt][nt][1]);
            *reinterpret_cast<float2*>(&g_sim[(size_t)(m + 8) * NCOLS + n]) =
                make_float2(acc[mt][nt][2], acc[mt][nt][3]);
        }
    }
}

// ---------------- kernel 3: dual masked softmax over p + combine ----------------
__global__ __launch_bounds__(256) void softmax_kernel(
    const float* __restrict__ cpred,
    const int* __restrict__ tmask,
    const int* __restrict__ vmask,
    const int* __restrict__ cmask,
    float* __restrict__ out, int wmm, int wcp)
{
    const int gw   = (int)((blockIdx.x * blockDim.x + threadIdx.x) >> 5);
    const int lane = threadIdx.x & 31;
    const int bq = gw >> 5;
    const int c  = gw & 31;
    const size_t base = (size_t)bq * NCOLS + c * P_DIM;
    const float NEG = __int_as_float(0xff800000);

    const bool tm = tmask[bq] != 0;
    float x[7], y[7];
    bool m1[7], m2[7];
    float mx = NEG, my = NEG;
    #pragma unroll
    for (int i = 0; i < 7; i++) {
        const int p = lane + 32 * i;
        if (p < P_DIM) {
            const bool vm = vmask[c * P_DIM + p] != 0;
            m1[i] = tm && vm;
            m2[i] = cmask[base + p] != 0;
            x[i] = m1[i] ? g_sim[base + p] : NEG;
            y[i] = m2[i] ? cpred[base + p] : NEG;
        } else { x[i] = NEG; y[i] = NEG; m1[i] = false; m2[i] = false; }
        mx = fmaxf(mx, x[i]); my = fmaxf(my, y[i]);
    }
    #pragma unroll
    for (int o = 16; o; o >>= 1) {
        mx = fmaxf(mx, __shfl_xor_sync(0xffffffffu, mx, o));
        my = fmaxf(my, __shfl_xor_sync(0xffffffffu, my, o));
    }
    float ex[7], ey[7], sx = 0.f, sy = 0.f;
    #pragma unroll
    for (int i = 0; i < 7; i++) {
        ex[i] = __expf(x[i] - mx);
        ey[i] = __expf(y[i] - my);
        if (lane + 32 * i < P_DIM) { sx += ex[i]; sy += ey[i]; }
    }
    #pragma unroll
    for (int o = 16; o; o >>= 1) {
        sx += __shfl_xor_sync(0xffffffffu, sx, o);
        sy += __shfl_xor_sync(0xffffffffu, sy, o);
    }
    const float rsx = 1.f / sx, rsy = 1.f / sy;
    #pragma unroll
    for (int i = 0; i < 7; i++) {
        const int p = lane + 32 * i;
        if (p < P_DIM) {
            const float mmv = ex[i] * rsx;
            const float cpv = ey[i] * rsy;
            out[base + p] = (m1[i] && m2[i]) ? 0.5f * (mmv + cpv) : 0.f;
            if (wmm) out[(size_t)N4 + base + p] = mmv;
            if (wcp) out[2 * (size_t)N4 + base + p] = cpv;
        }
    }
}

// ---------------- launch ----------------
extern "C" void kernel_launch(void* const* d_in, const int* in_sizes, int n_in,
                              void* d_out, int out_size)
{
    const float* visual_feat   = (const float*)d_in[0];
    const int*   visual_mask   = (const int*)d_in[1];
    const float* textual_feat  = (const float*)d_in[2];
    const int*   textual_mask  = (const int*)d_in[3];
    const float* concepts_pred = (const float*)d_in[4];
    const int*   concepts_mask = (const int*)d_in[5];
    float* out = (float*)d_out;

    const int wmm = (out_size >= 2 * N4) ? 1 : 0;
    const int wcp = (out_size >= 3 * N4) ? 1 : 0;

    normalize_kernel<<<MROWS + NCOLS, 256>>>(textual_feat, visual_feat);

    dim3 ggrid(NCOLS / 128, MROWS / 128);   // (49, 8)
    gemm_kernel<<<ggrid, 256>>>();

    softmax_kernel<<<4096, 256>>>(concepts_pred, textual_mask, visual_mask,
                                  concepts_mask, out, wmm, wcp);
}